// round 15
// baseline (speedup 1.0000x reference)
#include <cuda_runtime.h>
#include <cuda_bf16.h>
#include <cuda_fp16.h>
#include <cstdint>

#define N_NODES 100000
#define N_EDGES 1600000
#define D_IN    128
#define D_HID   256
#define N_CLS   10
#define NTILES  782                  // ceil(100000/128)
#define PAD_NODES (NTILES * 128)     // 100096
#define PAD_ROWS  (PAD_NODES - N_NODES)   // 96
#define SCAN_B    98                 // ceil(100000/1024)

// ---------------- scratch (no allocs allowed) ----------------
__device__ __align__(128) unsigned char g_x8[(size_t)N_NODES * 128];     // 12.8 MB (e4m3)
__device__ __align__(128) unsigned g_cnt[N_NODES];
__device__ __align__(128) unsigned g_off[N_NODES + 1];
__device__ __align__(128) unsigned g_wpos[N_NODES];
__device__ __align__(128) unsigned g_bsum[SCAN_B];
__device__ __align__(128) unsigned g_bpre[SCAN_B];
__device__ __align__(128) int g_srcs[N_EDGES];                           // 6.4 MB
__device__ __align__(128) float g_pooled[D_HID];
__device__ __align__(128) uint32_t g_Afrag[(size_t)PAD_NODES * 128];     // 51.2 MB
__device__ __align__(128) uint32_t g_Bfrag[32768];                       // 128 KB (hi only)
__device__ int g_idx32;

// ---- side stream + fork/join events, created at load time ----
static cudaStream_t g_s2;
static cudaEvent_t  g_evFork, g_evJoin;
namespace {
struct StreamInit {
    StreamInit() {
        cudaStreamCreateWithFlags(&g_s2, cudaStreamNonBlocking);
        cudaEventCreateWithFlags(&g_evFork, cudaEventDisableTiming);
        cudaEventCreateWithFlags(&g_evJoin, cudaEventDisableTiming);
    }
};
StreamInit g_stream_init;
}

// frag index for (n, c8, q):  c8 = k>>3 (0..31), q = pair-in-8 (0..3)
__device__ __forceinline__ uint32_t frag_idx(int n, int c8, int q) {
    int t = n >> 7, mt = (n >> 4) & 7;
    return (uint32_t)((((t * 16 + (c8 >> 1)) * 8 + mt) * 128)
         + ((n & 7) * 4 + q) * 4 + (c8 & 1) * 2 + ((n >> 3) & 1));
}

// fp8 helpers
__device__ __forceinline__ uint16_t f2_to_fp8x2(float hi, float lo) {
    uint16_t r;
    asm("cvt.rn.satfinite.e4m3x2.f32 %0, %1, %2;" : "=h"(r) : "f"(hi), "f"(lo));
    return r;
}
__device__ __forceinline__ __half2 fp8x2_to_h2(uint16_t v) {
    uint32_t r;
    asm("cvt.rn.f16x2.e4m3x2 %0, %1;" : "=r"(r) : "h"(v));
    return *(__half2*)&r;
}

// ---------------- probe edge_index dtype ----------------
__global__ void probe_kernel(const long long* __restrict__ ei64) {
    __shared__ int bad;
    if (threadIdx.x == 0) bad = 0;
    __syncthreads();
    long long v = ei64[threadIdx.x];
    if (v < 0 || v >= N_NODES) atomicOr(&bad, 1);
    __syncthreads();
    if (threadIdx.x == 0) g_idx32 = bad ? 1 : 0;
}

// ---------------- setup: zero counters + pooled + build B frags ----------------
__global__ __launch_bounds__(256) void setup_kernel(const float* __restrict__ Wl,
                                                    const float* __restrict__ Wr) {
    int i = blockIdx.x * blockDim.x + threadIdx.x;
    if (i < N_NODES) g_cnt[i] = 0u;
    if (i < D_HID) g_pooled[i] = 0.f;
    if (i < 32768) {
        int r  = i & 1;
        int l  = (i >> 1) & 31;
        int nt = (i >> 6) & 15;
        int ks = (i >> 10) & 15;
        int jh = (i >> 14) & 1;
        int n  = jh * 128 + nt * 8 + (l >> 2);
        int k  = ks * 16 + r * 8 + (l & 3) * 2;
        float w0 = (k < 128)     ? Wl[2 * D_HID * D_IN + n * D_IN + k]
                                 : Wr[2 * D_HID * D_IN + n * D_IN + (k - 128)];
        float w1 = (k + 1 < 128) ? Wl[2 * D_HID * D_IN + n * D_IN + k + 1]
                                 : Wr[2 * D_HID * D_IN + n * D_IN + (k + 1 - 128)];
        __nv_bfloat162 pk = __floats2bfloat162_rn(w0, w1);
        g_Bfrag[i] = *(const uint32_t*)&pk;
    }
}

// ---------------- convert: x -> {fp8 image, x-half A-frags} (side stream) ----------------
__global__ __launch_bounds__(256) void convert_kernel(const float* __restrict__ x) {
    size_t i0 = (size_t)blockIdx.x * blockDim.x + threadIdx.x;
    size_t stride = (size_t)gridDim.x * blockDim.x;

    const size_t NX = (size_t)PAD_NODES * 16;
    for (size_t j = i0; j < NX; j += stride) {
        int c8x = (int)(j & 15);
        int n   = (int)(j >> 4);
        int c8  = c8x + 16;
        uint32_t p[4] = {0, 0, 0, 0};
        if (n < N_NODES) {
            float4 a = __ldg((const float4*)(x + (size_t)n * D_IN + c8x * 8));
            float4 b = __ldg((const float4*)(x + (size_t)n * D_IN + c8x * 8 + 4));
            __nv_bfloat162 p0 = __floats2bfloat162_rn(a.x, a.y);
            __nv_bfloat162 p1 = __floats2bfloat162_rn(a.z, a.w);
            __nv_bfloat162 p2 = __floats2bfloat162_rn(b.x, b.y);
            __nv_bfloat162 p3 = __floats2bfloat162_rn(b.z, b.w);
            p[0] = *(uint32_t*)&p0; p[1] = *(uint32_t*)&p1;
            p[2] = *(uint32_t*)&p2; p[3] = *(uint32_t*)&p3;
            uint32_t lo = (uint32_t)f2_to_fp8x2(a.y, a.x)
                        | ((uint32_t)f2_to_fp8x2(a.w, a.z) << 16);
            uint32_t hi = (uint32_t)f2_to_fp8x2(b.y, b.x)
                        | ((uint32_t)f2_to_fp8x2(b.w, b.z) << 16);
            *(uint2*)(g_x8 + (size_t)n * 128 + c8x * 8) = make_uint2(lo, hi);
        }
#pragma unroll
        for (int q = 0; q < 4; q++) g_Afrag[frag_idx(n, c8, q)] = p[q];
    }
}

// ---------------- CSR pass 1: degree histogram (main stream) ----------------
__global__ __launch_bounds__(256) void hist_kernel(const void* __restrict__ ei_raw) {
    int e = blockIdx.x * blockDim.x + threadIdx.x;
    if (e >= N_EDGES) return;
    long long tgt = g_idx32 ? (long long)((const int*)ei_raw)[N_EDGES + e]
                            : ((const long long*)ei_raw)[(size_t)N_EDGES + e];
    if ((unsigned long long)tgt < N_NODES) atomicAdd(&g_cnt[tgt], 1u);
}

// ---------------- CSR scan phase 1 ----------------
__global__ __launch_bounds__(1024) void scan1_kernel() {
    __shared__ unsigned s[1024];
    int t = threadIdx.x;
    int n = blockIdx.x * 1024 + t;
    unsigned v = (n < N_NODES) ? g_cnt[n] : 0u;
    s[t] = v;
    __syncthreads();
    for (int off = 1; off < 1024; off <<= 1) {
        unsigned add = (t >= off) ? s[t - off] : 0u;
        __syncthreads();
        s[t] += add;
        __syncthreads();
    }
    if (n < N_NODES) g_off[n] = s[t] - v;
    if (t == 1023) g_bsum[blockIdx.x] = s[t];
}

// ---------------- CSR scan phase 2 ----------------
__global__ __launch_bounds__(128) void scan2_kernel() {
    __shared__ unsigned s[SCAN_B];
    int t = threadIdx.x;
    if (t < SCAN_B) s[t] = g_bsum[t];
    __syncthreads();
    if (t == 0) {
        unsigned run = 0;
        for (int i = 0; i < SCAN_B; i++) {
            unsigned c = s[i];
            s[i] = run;
            run += c;
        }
        g_off[N_NODES] = run;
    }
    __syncthreads();
    if (t < SCAN_B) g_bpre[t] = s[t];
}

// ---------------- CSR scan phase 3 ----------------
__global__ __launch_bounds__(1024) void scan3_kernel() {
    int n = blockIdx.x * 1024 + threadIdx.x;
    if (n >= N_NODES) return;
    unsigned o = g_off[n] + g_bpre[blockIdx.x];
    g_off[n] = o;
    g_wpos[n] = o;
}

// ---------------- CSR: scatter source indices ----------------
__global__ __launch_bounds__(256) void scatter_kernel(const void* __restrict__ ei_raw) {
    int e = blockIdx.x * blockDim.x + threadIdx.x;
    if (e >= N_EDGES) return;
    long long src, tgt;
    if (g_idx32) {
        src = ((const int*)ei_raw)[e];
        tgt = ((const int*)ei_raw)[N_EDGES + e];
    } else {
        src = ((const long long*)ei_raw)[e];
        tgt = ((const long long*)ei_raw)[(size_t)N_EDGES + e];
    }
    if ((unsigned long long)src >= N_NODES ||
        (unsigned long long)tgt >= N_NODES) return;
    unsigned pos = atomicAdd(&g_wpos[tgt], 1u);
    g_srcs[pos] = (int)src;
}

// ---------------- gather: 16 lanes/node (2 edge-halves x 8 col-lanes) ----------------
// Each half walks alternating CSR entries; shfl_xor(8) merges the halves.
__global__ __launch_bounds__(256) void gather_kernel() {
    const int l16  = threadIdx.x & 15;
    const int l8   = l16 & 7;
    const int half = l16 >> 3;
    const int g16 = (blockIdx.x * blockDim.x + threadIdx.x) >> 4;
    const int n16 = (gridDim.x * blockDim.x) >> 4;

    for (int n = g16; n < PAD_NODES; n += n16) {
        __half2 acc[8];
#pragma unroll
        for (int m = 0; m < 8; m++) acc[m] = __float2half2_rn(0.f);
        float inv = 0.f;

        if (n < N_NODES) {
            int beg = (int)g_off[n];
            int end = (int)g_off[n + 1];
            int i = beg + half;
            // stride-2 walk, 2-unrolled (process i and i+2)
            for (; i + 2 < end; i += 4) {
                int s0 = __ldg(g_srcs + i);
                int s1 = __ldg(g_srcs + i + 2);
                uint4 v0 = __ldg((const uint4*)(g_x8 + (size_t)s0 * 128) + l8);
                uint4 v1 = __ldg((const uint4*)(g_x8 + (size_t)s1 * 128) + l8);
                const uint32_t w0[4] = { v0.x, v0.y, v0.z, v0.w };
                const uint32_t w1[4] = { v1.x, v1.y, v1.z, v1.w };
#pragma unroll
                for (int m = 0; m < 4; m++) {
                    acc[2 * m]     = __hadd2(acc[2 * m],     fp8x2_to_h2((uint16_t)(w0[m] & 0xffffu)));
                    acc[2 * m + 1] = __hadd2(acc[2 * m + 1], fp8x2_to_h2((uint16_t)(w0[m] >> 16)));
                    acc[2 * m]     = __hadd2(acc[2 * m],     fp8x2_to_h2((uint16_t)(w1[m] & 0xffffu)));
                    acc[2 * m + 1] = __hadd2(acc[2 * m + 1], fp8x2_to_h2((uint16_t)(w1[m] >> 16)));
                }
            }
            if (i < end) {
                int s0 = __ldg(g_srcs + i);
                uint4 v0 = __ldg((const uint4*)(g_x8 + (size_t)s0 * 128) + l8);
                const uint32_t w0[4] = { v0.x, v0.y, v0.z, v0.w };
#pragma unroll
                for (int m = 0; m < 4; m++) {
                    acc[2 * m]     = __hadd2(acc[2 * m],     fp8x2_to_h2((uint16_t)(w0[m] & 0xffffu)));
                    acc[2 * m + 1] = __hadd2(acc[2 * m + 1], fp8x2_to_h2((uint16_t)(w0[m] >> 16)));
                }
            }
            inv = 1.0f / fmaxf((float)(end - beg), 1.0f);
        }

        // merge the two edge-halves (lanes l and l^8 belong to the same node)
#pragma unroll
        for (int m = 0; m < 8; m++) {
            uint32_t u = *(uint32_t*)&acc[m];
            uint32_t o = __shfl_xor_sync(0xffffffffu, u, 8);
            acc[m] = __hadd2(acc[m], *(__half2*)&o);
        }

        if (half == 0) {
#pragma unroll
            for (int m = 0; m < 4; m++) {
                float2 fa = __half22float2(acc[2 * m]);
                float2 fb = __half22float2(acc[2 * m + 1]);
                __nv_bfloat162 pa = __floats2bfloat162_rn(fa.x * inv, fa.y * inv);
                __nv_bfloat162 pb = __floats2bfloat162_rn(fb.x * inv, fb.y * inv);
                int c8 = l8 * 2 + (m >> 1);
                int q  = (m & 1) * 2;
                g_Afrag[frag_idx(n, c8, q)]     = *(const uint32_t*)&pa;
                g_Afrag[frag_idx(n, c8, q + 1)] = *(const uint32_t*)&pb;
            }
        }
    }
}

// ---------------- mma.sync GEMM + bias + relu + pool ----------------
#define MMA16816(d, a, b) \
    asm volatile("mma.sync.aligned.m16n8k16.row.col.f32.bf16.bf16.f32 " \
        "{%0,%1,%2,%3}, {%4,%5,%6,%7}, {%8,%9}, {%0,%1,%2,%3};" \
        : "+f"((d)[0]), "+f"((d)[1]), "+f"((d)[2]), "+f"((d)[3]) \
        : "r"((a)[0]), "r"((a)[1]), "r"((a)[2]), "r"((a)[3]), \
          "r"((b)[0]), "r"((b)[1]))

// 296 CTAs x 256 threads, 2 CTAs/SM. Warp tile 64x32. A double-buffered in regs.
__global__ __launch_bounds__(256, 2) void gemm_mma_kernel(const float* __restrict__ bias) {
    extern __shared__ uint32_t sB[];     // 16384 u32 = 64 KB (one jhalf, hi)
    const int tid = threadIdx.x;
    const int lane = tid & 31, wid = tid >> 5;
    const int wm = wid >> 2, wn = wid & 3;     // wm 0..1, wn 0..3
    const int jhalf = blockIdx.x & 1;
    const int cbase = blockIdx.x >> 1;         // 0..147

    {
        const uint4* src = (const uint4*)(g_Bfrag + jhalf * 16384);
        uint4* dst = (uint4*)sB;
        for (int i = tid; i < 16384 / 4; i += 256) dst[i] = __ldg(src + i);
    }
    __syncthreads();

    float br[4][2];
#pragma unroll
    for (int ntl = 0; ntl < 4; ntl++) {
        int col = jhalf * 128 + wn * 32 + ntl * 8 + (lane & 3) * 2;
        br[ntl][0] = __ldg(bias + 2 * D_HID + col);
        br[ntl][1] = __ldg(bias + 2 * D_HID + col + 1);
    }

    float pool[4][2] = {};

    for (int t = cbase; t < NTILES; t += 148) {
        float acc[4][4][4];
#pragma unroll
        for (int ml = 0; ml < 4; ml++)
#pragma unroll
            for (int ntl = 0; ntl < 4; ntl++)
#pragma unroll
                for (int q = 0; q < 4; q++) acc[ml][ntl][q] = 0.f;

        const uint32_t* abase = g_Afrag + (size_t)t * (16 * 8 * 128);

        uint4 a[2][4];
#pragma unroll
        for (int ml = 0; ml < 4; ml++)
            a[0][ml] = __ldg((const uint4*)(abase + (wm * 4 + ml) * 128 + lane * 4));

#pragma unroll 4
        for (int ks = 0; ks < 16; ks++) {
            int cur = ks & 1;
            if (ks < 15) {
#pragma unroll
                for (int ml = 0; ml < 4; ml++)
                    a[cur ^ 1][ml] = __ldg((const uint4*)(abase + (((ks + 1) * 8) + (wm * 4 + ml)) * 128 + lane * 4));
            }
#pragma unroll
            for (int ntl = 0; ntl < 4; ntl++) {
                uint2 bv = *(const uint2*)(sB + ((ks * 16 + wn * 4 + ntl) * 32 + lane) * 2);
                uint32_t b[2] = { bv.x, bv.y };
#pragma unroll
                for (int ml = 0; ml < 4; ml++) {
                    uint32_t ar[4] = { a[cur][ml].x, a[cur][ml].y, a[cur][ml].z, a[cur][ml].w };
                    MMA16816(acc[ml][ntl], ar, b);
                }
            }
        }

#pragma unroll
        for (int ml = 0; ml < 4; ml++)
#pragma unroll
            for (int ntl = 0; ntl < 4; ntl++) {
                pool[ntl][0] += fmaxf(acc[ml][ntl][0] + br[ntl][0], 0.f)
                              + fmaxf(acc[ml][ntl][2] + br[ntl][0], 0.f);
                pool[ntl][1] += fmaxf(acc[ml][ntl][1] + br[ntl][1], 0.f)
                              + fmaxf(acc[ml][ntl][3] + br[ntl][1], 0.f);
            }
    }

#pragma unroll
    for (int ntl = 0; ntl < 4; ntl++)
#pragma unroll
        for (int c = 0; c < 2; c++) {
            float v = pool[ntl][c];
            v += __shfl_xor_sync(0xffffffffu, v, 16);
            v += __shfl_xor_sync(0xffffffffu, v, 8);
            v += __shfl_xor_sync(0xffffffffu, v, 4);
            if ((lane >> 2) == 0) {
                int col = jhalf * 128 + wn * 32 + ntl * 8 + (lane & 3) * 2 + c;
                atomicAdd(&g_pooled[col], v);
            }
        }
}

// ---------------- head: pad-correction, mean, MLP, log_softmax ----------------
__global__ __launch_bounds__(320) void head_kernel(
    const float* __restrict__ bias,
    const float* __restrict__ W1, const float* __restrict__ b1,
    const float* __restrict__ W2, const float* __restrict__ b2,
    float* __restrict__ out)
{
    __shared__ float pm[D_HID];
    __shared__ float z1[D_HID];
    __shared__ float z2[N_CLS];
    int t = threadIdx.x;

    if (t < D_HID) {
        float pad = (float)PAD_ROWS * fmaxf(bias[2 * D_HID + t], 0.f);
        pm[t] = (g_pooled[t] - pad) * (1.0f / (float)N_NODES);
    }
    __syncthreads();

    if (t < D_HID) {
        float s = b1[t];
        const float* w = W1 + t * D_HID;
#pragma unroll 8
        for (int j = 0; j < D_HID; j++) s = fmaf(w[j], pm[j], s);
        z1[t] = fmaxf(s, 0.f);
    }
    __syncthreads();

    int wrp = t >> 5, lane = t & 31;
    if (wrp < N_CLS) {
        float s2 = 0.f;
        for (int i = lane; i < D_HID; i += 32) s2 = fmaf(W2[wrp * D_HID + i], z1[i], s2);
#pragma unroll
        for (int o = 16; o; o >>= 1) s2 += __shfl_xor_sync(0xffffffffu, s2, o);
        if (lane == 0) z2[wrp] = s2 + b2[wrp];
    }
    __syncthreads();

    if (t == 0) {
        float m = z2[0];
#pragma unroll
        for (int c = 1; c < N_CLS; c++) m = fmaxf(m, z2[c]);
        float se = 0.f;
#pragma unroll
        for (int c = 0; c < N_CLS; c++) se += expf(z2[c] - m);
        float lse = logf(se);
#pragma unroll
        for (int c = 0; c < N_CLS; c++) out[c] = z2[c] - m - lse;
    }
}

// ---------------- launch ----------------
extern "C" void kernel_launch(void* const* d_in, const int* in_sizes, int n_in,
                              void* d_out, int out_size)
{
    const float* x    = (const float*)d_in[0];
    const void*  ei   = d_in[1];
    const float* Wl   = (const float*)d_in[2];
    const float* Wr   = (const float*)d_in[3];
    const float* bias = (const float*)d_in[4];
    const float* W1   = (const float*)d_in[5];
    const float* b1   = (const float*)d_in[6];
    const float* W2   = (const float*)d_in[7];
    const float* b2   = (const float*)d_in[8];
    float* out = (float*)d_out;

    const int EB = (N_EDGES + 255) / 256;

    probe_kernel<<<1, 1024>>>((const long long*)ei);
    setup_kernel<<<(N_NODES + 255) / 256, 256>>>(Wl, Wr);

    // fork: convert on side stream, CSR chain on main stream
    cudaEventRecord(g_evFork, 0);
    cudaStreamWaitEvent(g_s2, g_evFork, 0);
    convert_kernel<<<1184, 256, 0, g_s2>>>(x);

    hist_kernel<<<EB, 256>>>(ei);
    scan1_kernel<<<SCAN_B, 1024>>>();
    scan2_kernel<<<1, 128>>>();
    scan3_kernel<<<SCAN_B, 1024>>>();
    scatter_kernel<<<EB, 256>>>(ei);

    // join
    cudaEventRecord(g_evJoin, g_s2);
    cudaStreamWaitEvent(0, g_evJoin, 0);

    gather_kernel<<<1184, 256>>>();

    cudaFuncSetAttribute(gemm_mma_kernel,
                         cudaFuncAttributeMaxDynamicSharedMemorySize, 65536);
    gemm_mma_kernel<<<296, 256, 65536>>>(bias);

    head_kernel<<<1, 320>>>(bias, W1, b1, W2, b2, out);
}

// round 16
// speedup vs baseline: 1.0262x; 1.0262x over previous
#include <cuda_runtime.h>
#include <cuda_bf16.h>
#include <cuda_fp16.h>
#include <cstdint>

#define N_NODES 100000
#define N_EDGES 1600000
#define D_IN    128
#define D_HID   256
#define N_CLS   10
#define NTILES  782                  // ceil(100000/128)
#define PAD_NODES (NTILES * 128)     // 100096
#define PAD_ROWS  (PAD_NODES - N_NODES)   // 96
#define SCAN_B    98                 // ceil(100000/1024)

// ---------------- scratch (no allocs allowed) ----------------
__device__ __align__(128) unsigned char g_x8[(size_t)N_NODES * 128];     // 12.8 MB (e4m3)
__device__ __align__(128) unsigned g_cnt[N_NODES];
__device__ __align__(128) unsigned g_off[N_NODES + 1];
__device__ __align__(128) unsigned g_wpos[N_NODES];
__device__ __align__(128) unsigned g_bsum[SCAN_B];
__device__ __align__(128) unsigned g_bpre[SCAN_B];
__device__ __align__(128) int g_srcs[N_EDGES];                           // 6.4 MB
__device__ __align__(128) float g_pooled[D_HID];
__device__ __align__(128) uint32_t g_Afrag[(size_t)PAD_NODES * 128];     // 51.2 MB
__device__ __align__(128) uint32_t g_Bfrag[32768];                       // 128 KB (hi only)
__device__ int g_idx32;

// ---- side stream + fork/join events, created at load time ----
static cudaStream_t g_s2;
static cudaEvent_t  g_evFork, g_evJoin;
namespace {
struct StreamInit {
    StreamInit() {
        cudaStreamCreateWithFlags(&g_s2, cudaStreamNonBlocking);
        cudaEventCreateWithFlags(&g_evFork, cudaEventDisableTiming);
        cudaEventCreateWithFlags(&g_evJoin, cudaEventDisableTiming);
    }
};
StreamInit g_stream_init;
}

// frag index for (n, c8, q):  c8 = k>>3 (0..31), q = pair-in-8 (0..3)
__device__ __forceinline__ uint32_t frag_idx(int n, int c8, int q) {
    int t = n >> 7, mt = (n >> 4) & 7;
    return (uint32_t)((((t * 16 + (c8 >> 1)) * 8 + mt) * 128)
         + ((n & 7) * 4 + q) * 4 + (c8 & 1) * 2 + ((n >> 3) & 1));
}

// fp8 helpers
__device__ __forceinline__ uint16_t f2_to_fp8x2(float hi, float lo) {
    uint16_t r;
    asm("cvt.rn.satfinite.e4m3x2.f32 %0, %1, %2;" : "=h"(r) : "f"(hi), "f"(lo));
    return r;
}
__device__ __forceinline__ __half2 fp8x2_to_h2(uint16_t v) {
    uint32_t r;
    asm("cvt.rn.f16x2.e4m3x2 %0, %1;" : "=r"(r) : "h"(v));
    return *(__half2*)&r;
}

// ---------------- probe edge_index dtype ----------------
__global__ void probe_kernel(const long long* __restrict__ ei64) {
    __shared__ int bad;
    if (threadIdx.x == 0) bad = 0;
    __syncthreads();
    long long v = ei64[threadIdx.x];
    if (v < 0 || v >= N_NODES) atomicOr(&bad, 1);
    __syncthreads();
    if (threadIdx.x == 0) g_idx32 = bad ? 1 : 0;
}

// ---------------- setup: zero counters + pooled + build B frags ----------------
__global__ __launch_bounds__(256) void setup_kernel(const float* __restrict__ Wl,
                                                    const float* __restrict__ Wr) {
    int i = blockIdx.x * blockDim.x + threadIdx.x;
    if (i < N_NODES) g_cnt[i] = 0u;
    if (i < D_HID) g_pooled[i] = 0.f;
    if (i < 32768) {
        int r  = i & 1;
        int l  = (i >> 1) & 31;
        int nt = (i >> 6) & 15;
        int ks = (i >> 10) & 15;
        int jh = (i >> 14) & 1;
        int n  = jh * 128 + nt * 8 + (l >> 2);
        int k  = ks * 16 + r * 8 + (l & 3) * 2;
        float w0 = (k < 128)     ? Wl[2 * D_HID * D_IN + n * D_IN + k]
                                 : Wr[2 * D_HID * D_IN + n * D_IN + (k - 128)];
        float w1 = (k + 1 < 128) ? Wl[2 * D_HID * D_IN + n * D_IN + k + 1]
                                 : Wr[2 * D_HID * D_IN + n * D_IN + (k + 1 - 128)];
        __nv_bfloat162 pk = __floats2bfloat162_rn(w0, w1);
        g_Bfrag[i] = *(const uint32_t*)&pk;
    }
}

// ---------------- convert: x -> {fp8 image, x-half A-frags} (side stream) ----------------
__global__ __launch_bounds__(256) void convert_kernel(const float* __restrict__ x) {
    size_t i0 = (size_t)blockIdx.x * blockDim.x + threadIdx.x;
    size_t stride = (size_t)gridDim.x * blockDim.x;

    const size_t NX = (size_t)PAD_NODES * 16;
    for (size_t j = i0; j < NX; j += stride) {
        int c8x = (int)(j & 15);
        int n   = (int)(j >> 4);
        int c8  = c8x + 16;
        uint32_t p[4] = {0, 0, 0, 0};
        if (n < N_NODES) {
            float4 a = __ldg((const float4*)(x + (size_t)n * D_IN + c8x * 8));
            float4 b = __ldg((const float4*)(x + (size_t)n * D_IN + c8x * 8 + 4));
            __nv_bfloat162 p0 = __floats2bfloat162_rn(a.x, a.y);
            __nv_bfloat162 p1 = __floats2bfloat162_rn(a.z, a.w);
            __nv_bfloat162 p2 = __floats2bfloat162_rn(b.x, b.y);
            __nv_bfloat162 p3 = __floats2bfloat162_rn(b.z, b.w);
            p[0] = *(uint32_t*)&p0; p[1] = *(uint32_t*)&p1;
            p[2] = *(uint32_t*)&p2; p[3] = *(uint32_t*)&p3;
            uint32_t lo = (uint32_t)f2_to_fp8x2(a.y, a.x)
                        | ((uint32_t)f2_to_fp8x2(a.w, a.z) << 16);
            uint32_t hi = (uint32_t)f2_to_fp8x2(b.y, b.x)
                        | ((uint32_t)f2_to_fp8x2(b.w, b.z) << 16);
            *(uint2*)(g_x8 + (size_t)n * 128 + c8x * 8) = make_uint2(lo, hi);
        }
#pragma unroll
        for (int q = 0; q < 4; q++) g_Afrag[frag_idx(n, c8, q)] = p[q];
    }
}

// ---------------- CSR pass 1: degree histogram (main stream) ----------------
__global__ __launch_bounds__(256) void hist_kernel(const void* __restrict__ ei_raw) {
    int e = blockIdx.x * blockDim.x + threadIdx.x;
    if (e >= N_EDGES) return;
    long long tgt = g_idx32 ? (long long)((const int*)ei_raw)[N_EDGES + e]
                            : ((const long long*)ei_raw)[(size_t)N_EDGES + e];
    if ((unsigned long long)tgt < N_NODES) atomicAdd(&g_cnt[tgt], 1u);
}

// ---------------- CSR scan phase 1 ----------------
__global__ __launch_bounds__(1024) void scan1_kernel() {
    __shared__ unsigned s[1024];
    int t = threadIdx.x;
    int n = blockIdx.x * 1024 + t;
    unsigned v = (n < N_NODES) ? g_cnt[n] : 0u;
    s[t] = v;
    __syncthreads();
    for (int off = 1; off < 1024; off <<= 1) {
        unsigned add = (t >= off) ? s[t - off] : 0u;
        __syncthreads();
        s[t] += add;
        __syncthreads();
    }
    if (n < N_NODES) g_off[n] = s[t] - v;
    if (t == 1023) g_bsum[blockIdx.x] = s[t];
}

// ---------------- CSR scan phase 2 ----------------
__global__ __launch_bounds__(128) void scan2_kernel() {
    __shared__ unsigned s[SCAN_B];
    int t = threadIdx.x;
    if (t < SCAN_B) s[t] = g_bsum[t];
    __syncthreads();
    if (t == 0) {
        unsigned run = 0;
        for (int i = 0; i < SCAN_B; i++) {
            unsigned c = s[i];
            s[i] = run;
            run += c;
        }
        g_off[N_NODES] = run;
    }
    __syncthreads();
    if (t < SCAN_B) g_bpre[t] = s[t];
}

// ---------------- CSR scan phase 3 ----------------
__global__ __launch_bounds__(1024) void scan3_kernel() {
    int n = blockIdx.x * 1024 + threadIdx.x;
    if (n >= N_NODES) return;
    unsigned o = g_off[n] + g_bpre[blockIdx.x];
    g_off[n] = o;
    g_wpos[n] = o;
}

// ---------------- CSR: scatter source indices ----------------
__global__ __launch_bounds__(256) void scatter_kernel(const void* __restrict__ ei_raw) {
    int e = blockIdx.x * blockDim.x + threadIdx.x;
    if (e >= N_EDGES) return;
    long long src, tgt;
    if (g_idx32) {
        src = ((const int*)ei_raw)[e];
        tgt = ((const int*)ei_raw)[N_EDGES + e];
    } else {
        src = ((const long long*)ei_raw)[e];
        tgt = ((const long long*)ei_raw)[(size_t)N_EDGES + e];
    }
    if ((unsigned long long)src >= N_NODES ||
        (unsigned long long)tgt >= N_NODES) return;
    unsigned pos = atomicAdd(&g_wpos[tgt], 1u);
    g_srcs[pos] = (int)src;
}

// ---------------- gather: fp8 neighbors, f16x2 accumulate, bf16 frags ----------------
// 8 lanes per node; lane l8 owns cols [l8*16, l8*16+16). 4 rows in flight.
__global__ __launch_bounds__(256) void gather_kernel() {
    const int l8 = threadIdx.x & 7;
    const int g8 = (blockIdx.x * blockDim.x + threadIdx.x) >> 3;
    const int n8 = (gridDim.x * blockDim.x) >> 3;

    for (int n = g8; n < PAD_NODES; n += n8) {
        __half2 acc[8];
#pragma unroll
        for (int m = 0; m < 8; m++) acc[m] = __float2half2_rn(0.f);
        float inv = 0.f;

        if (n < N_NODES) {
            int beg = (int)g_off[n];
            int end = (int)g_off[n + 1];
            int i = beg;
            for (; i + 4 <= end; i += 4) {
                int s0 = __ldg(g_srcs + i);
                int s1 = __ldg(g_srcs + i + 1);
                int s2 = __ldg(g_srcs + i + 2);
                int s3 = __ldg(g_srcs + i + 3);
                uint4 v0 = __ldg((const uint4*)(g_x8 + (size_t)s0 * 128) + l8);
                uint4 v1 = __ldg((const uint4*)(g_x8 + (size_t)s1 * 128) + l8);
                uint4 v2 = __ldg((const uint4*)(g_x8 + (size_t)s2 * 128) + l8);
                uint4 v3 = __ldg((const uint4*)(g_x8 + (size_t)s3 * 128) + l8);
                const uint32_t w0[4] = { v0.x, v0.y, v0.z, v0.w };
                const uint32_t w1[4] = { v1.x, v1.y, v1.z, v1.w };
                const uint32_t w2[4] = { v2.x, v2.y, v2.z, v2.w };
                const uint32_t w3[4] = { v3.x, v3.y, v3.z, v3.w };
#pragma unroll
                for (int m = 0; m < 4; m++) {
                    acc[2 * m]     = __hadd2(acc[2 * m],     fp8x2_to_h2((uint16_t)(w0[m] & 0xffffu)));
                    acc[2 * m + 1] = __hadd2(acc[2 * m + 1], fp8x2_to_h2((uint16_t)(w0[m] >> 16)));
                    acc[2 * m]     = __hadd2(acc[2 * m],     fp8x2_to_h2((uint16_t)(w1[m] & 0xffffu)));
                    acc[2 * m + 1] = __hadd2(acc[2 * m + 1], fp8x2_to_h2((uint16_t)(w1[m] >> 16)));
                    acc[2 * m]     = __hadd2(acc[2 * m],     fp8x2_to_h2((uint16_t)(w2[m] & 0xffffu)));
                    acc[2 * m + 1] = __hadd2(acc[2 * m + 1], fp8x2_to_h2((uint16_t)(w2[m] >> 16)));
                    acc[2 * m]     = __hadd2(acc[2 * m],     fp8x2_to_h2((uint16_t)(w3[m] & 0xffffu)));
                    acc[2 * m + 1] = __hadd2(acc[2 * m + 1], fp8x2_to_h2((uint16_t)(w3[m] >> 16)));
                }
            }
            for (; i < end; i++) {
                int s0 = __ldg(g_srcs + i);
                uint4 v0 = __ldg((const uint4*)(g_x8 + (size_t)s0 * 128) + l8);
                const uint32_t w0[4] = { v0.x, v0.y, v0.z, v0.w };
#pragma unroll
                for (int m = 0; m < 4; m++) {
                    acc[2 * m]     = __hadd2(acc[2 * m],     fp8x2_to_h2((uint16_t)(w0[m] & 0xffffu)));
                    acc[2 * m + 1] = __hadd2(acc[2 * m + 1], fp8x2_to_h2((uint16_t)(w0[m] >> 16)));
                }
            }
            inv = 1.0f / fmaxf((float)(end - beg), 1.0f);
        }

#pragma unroll
        for (int m = 0; m < 4; m++) {
            float2 fa = __half22float2(acc[2 * m]);
            float2 fb = __half22float2(acc[2 * m + 1]);
            __nv_bfloat162 pa = __floats2bfloat162_rn(fa.x * inv, fa.y * inv);
            __nv_bfloat162 pb = __floats2bfloat162_rn(fb.x * inv, fb.y * inv);
            int c8 = l8 * 2 + (m >> 1);
            int q  = (m & 1) * 2;
            g_Afrag[frag_idx(n, c8, q)]     = *(const uint32_t*)&pa;
            g_Afrag[frag_idx(n, c8, q + 1)] = *(const uint32_t*)&pb;
        }
    }
}

// ---------------- mma.sync GEMM + bias + relu + pool ----------------
#define MMA16816(d, a, b) \
    asm volatile("mma.sync.aligned.m16n8k16.row.col.f32.bf16.bf16.f32 " \
        "{%0,%1,%2,%3}, {%4,%5,%6,%7}, {%8,%9}, {%0,%1,%2,%3};" \
        : "+f"((d)[0]), "+f"((d)[1]), "+f"((d)[2]), "+f"((d)[3]) \
        : "r"((a)[0]), "r"((a)[1]), "r"((a)[2]), "r"((a)[3]), \
          "r"((b)[0]), "r"((b)[1]))

// 296 CTAs x 256 threads, 2 CTAs/SM. Warp grid 2M x 4N, warp tile 64x32.
__global__ __launch_bounds__(256, 2) void gemm_mma_kernel(const float* __restrict__ bias) {
    extern __shared__ uint32_t sB[];     // 16384 u32 = 64 KB (one jhalf, hi)
    const int tid = threadIdx.x;
    const int lane = tid & 31, wid = tid >> 5;
    const int wm = wid >> 2, wn = wid & 3;     // wm 0..1, wn 0..3
    const int jhalf = blockIdx.x & 1;
    const int cbase = blockIdx.x >> 1;         // 0..147

    {
        const uint4* src = (const uint4*)(g_Bfrag + jhalf * 16384);
        uint4* dst = (uint4*)sB;
        for (int i = tid; i < 16384 / 4; i += 256) dst[i] = __ldg(src + i);
    }
    __syncthreads();

    float br[4][2];
#pragma unroll
    for (int ntl = 0; ntl < 4; ntl++) {
        int col = jhalf * 128 + wn * 32 + ntl * 8 + (lane & 3) * 2;
        br[ntl][0] = __ldg(bias + 2 * D_HID + col);
        br[ntl][1] = __ldg(bias + 2 * D_HID + col + 1);
    }

    float pool[4][2] = {};

    for (int t = cbase; t < NTILES; t += 148) {
        float acc[4][4][4];
#pragma unroll
        for (int ml = 0; ml < 4; ml++)
#pragma unroll
            for (int ntl = 0; ntl < 4; ntl++)
#pragma unroll
                for (int q = 0; q < 4; q++) acc[ml][ntl][q] = 0.f;

        const uint32_t* abase = g_Afrag + (size_t)t * (16 * 8 * 128);
#pragma unroll 2
        for (int ks = 0; ks < 16; ks++) {
            uint32_t a[4][4];
#pragma unroll
            for (int ml = 0; ml < 4; ml++) {
                uint4 v = __ldg((const uint4*)(abase + ((ks * 8) + (wm * 4 + ml)) * 128 + lane * 4));
                a[ml][0] = v.x; a[ml][1] = v.y; a[ml][2] = v.z; a[ml][3] = v.w;
            }
#pragma unroll
            for (int ntl = 0; ntl < 4; ntl++) {
                uint2 bv = *(const uint2*)(sB + ((ks * 16 + wn * 4 + ntl) * 32 + lane) * 2);
                uint32_t b[2] = { bv.x, bv.y };
#pragma unroll
                for (int ml = 0; ml < 4; ml++) MMA16816(acc[ml][ntl], a[ml], b);
            }
        }

#pragma unroll
        for (int ml = 0; ml < 4; ml++)
#pragma unroll
            for (int ntl = 0; ntl < 4; ntl++) {
                pool[ntl][0] += fmaxf(acc[ml][ntl][0] + br[ntl][0], 0.f)
                              + fmaxf(acc[ml][ntl][2] + br[ntl][0], 0.f);
                pool[ntl][1] += fmaxf(acc[ml][ntl][1] + br[ntl][1], 0.f)
                              + fmaxf(acc[ml][ntl][3] + br[ntl][1], 0.f);
            }
    }

#pragma unroll
    for (int ntl = 0; ntl < 4; ntl++)
#pragma unroll
        for (int c = 0; c < 2; c++) {
            float v = pool[ntl][c];
            v += __shfl_xor_sync(0xffffffffu, v, 16);
            v += __shfl_xor_sync(0xffffffffu, v, 8);
            v += __shfl_xor_sync(0xffffffffu, v, 4);
            if ((lane >> 2) == 0) {
                int col = jhalf * 128 + wn * 32 + ntl * 8 + (lane & 3) * 2 + c;
                atomicAdd(&g_pooled[col], v);
            }
        }
}

// ---------------- head: pad-correction, mean, MLP, log_softmax ----------------
__global__ __launch_bounds__(320) void head_kernel(
    const float* __restrict__ bias,
    const float* __restrict__ W1, const float* __restrict__ b1,
    const float* __restrict__ W2, const float* __restrict__ b2,
    float* __restrict__ out)
{
    __shared__ float pm[D_HID];
    __shared__ float z1[D_HID];
    __shared__ float z2[N_CLS];
    int t = threadIdx.x;

    if (t < D_HID) {
        float pad = (float)PAD_ROWS * fmaxf(bias[2 * D_HID + t], 0.f);
        pm[t] = (g_pooled[t] - pad) * (1.0f / (float)N_NODES);
    }
    __syncthreads();

    if (t < D_HID) {
        float s = b1[t];
        const float* w = W1 + t * D_HID;
#pragma unroll 8
        for (int j = 0; j < D_HID; j++) s = fmaf(w[j], pm[j], s);
        z1[t] = fmaxf(s, 0.f);
    }
    __syncthreads();

    int wrp = t >> 5, lane = t & 31;
    if (wrp < N_CLS) {
        float s2 = 0.f;
        for (int i = lane; i < D_HID; i += 32) s2 = fmaf(W2[wrp * D_HID + i], z1[i], s2);
#pragma unroll
        for (int o = 16; o; o >>= 1) s2 += __shfl_xor_sync(0xffffffffu, s2, o);
        if (lane == 0) z2[wrp] = s2 + b2[wrp];
    }
    __syncthreads();

    if (t == 0) {
        float m = z2[0];
#pragma unroll
        for (int c = 1; c < N_CLS; c++) m = fmaxf(m, z2[c]);
        float se = 0.f;
#pragma unroll
        for (int c = 0; c < N_CLS; c++) se += expf(z2[c] - m);
        float lse = logf(se);
#pragma unroll
        for (int c = 0; c < N_CLS; c++) out[c] = z2[c] - m - lse;
    }
}

// ---------------- launch ----------------
extern "C" void kernel_launch(void* const* d_in, const int* in_sizes, int n_in,
                              void* d_out, int out_size)
{
    const float* x    = (const float*)d_in[0];
    const void*  ei   = d_in[1];
    const float* Wl   = (const float*)d_in[2];
    const float* Wr   = (const float*)d_in[3];
    const float* bias = (const float*)d_in[4];
    const float* W1   = (const float*)d_in[5];
    const float* b1   = (const float*)d_in[6];
    const float* W2   = (const float*)d_in[7];
    const float* b2   = (const float*)d_in[8];
    float* out = (float*)d_out;

    const int EB = (N_EDGES + 255) / 256;

    probe_kernel<<<1, 1024>>>((const long long*)ei);
    setup_kernel<<<(N_NODES + 255) / 256, 256>>>(Wl, Wr);

    // fork: convert on side stream, CSR chain on main stream
    cudaEventRecord(g_evFork, 0);
    cudaStreamWaitEvent(g_s2, g_evFork, 0);
    convert_kernel<<<1184, 256, 0, g_s2>>>(x);

    hist_kernel<<<EB, 256>>>(ei);
    scan1_kernel<<<SCAN_B, 1024>>>();
    scan2_kernel<<<1, 128>>>();
    scan3_kernel<<<SCAN_B, 1024>>>();
    scatter_kernel<<<EB, 256>>>(ei);

    // join
    cudaEventRecord(g_evJoin, g_s2);
    cudaStreamWaitEvent(0, g_evJoin, 0);

    gather_kernel<<<1184, 256>>>();

    cudaFuncSetAttribute(gemm_mma_kernel,
                         cudaFuncAttributeMaxDynamicSharedMemorySize, 65536);
    gemm_mma_kernel<<<296, 256, 65536>>>(bias);

    head_kernel<<<1, 320>>>(bias, W1, b1, W2, b2, out);
}